// round 17
// baseline (speedup 1.0000x reference)
#include <cuda_runtime.h>
#include <cuda_bf16.h>
#include <cooperative_groups.h>
#include <math.h>
#include <stdint.h>

namespace cg = cooperative_groups;

// ---------------- problem constants ----------------
#define NB 2
#define NN 16384
#define CIN 64
#define NP 2048
#define NS 32
#define CD 256
#define KP1 80                  // 3+64=67 padded to 80
#define NROWS (NB*NP*NS)        // 131072

// FPS cluster config
#define FT 256                  // threads per FPS CTA
#define NW (FT / 32)            // 8 warps
#define CLS 8                   // cluster size (CTAs per batch)
#define SHARD (NN / CLS)        // 2048 points owned per CTA
#define SLOTS (SHARD / FT)      // 8 slots per thread (register-resident coords)
#define NKEY (NW * CLS)         // 64 candidate keys per iteration
#define FPS_SMEM (NN * 12)      // full copy: float2 xy + float z = 196608 B

// ---------------- scratch (device globals; no allocation allowed) ----------------
__device__ alignas(256) int   g_samp[NB * NP];
__device__ alignas(256) float g_newxyz[NB * NP * 3];
__device__ alignas(256) int   g_nn[NROWS];
__device__ alignas(256) float g_featT[(size_t)NB * NN * CIN];
__device__ alignas(256) float g_Wp1[64 * KP1];
__device__ alignas(256) float g_G[(size_t)NROWS * KP1];
__device__ alignas(256) float g_H1[(size_t)NROWS * 64];
__device__ alignas(256) float g_H2[(size_t)NROWS * 128];
__device__ alignas(256) float g_xh[(size_t)NB * NP * CD];   // (b,p,c)
__device__ alignas(256) float g_qt[(size_t)NB * CD * CD];
__device__ alignas(256) float g_kt[(size_t)NB * CD * CD];
__device__ alignas(256) float g_aff[(size_t)NB * CD * CD];
__device__ alignas(256) float g_s[NB * CD];
__device__ alignas(256) float g_e[NB * CD];

// ---------------- small PTX helpers ----------------
__device__ __forceinline__ uint32_t smem_u32(const void* p) {
    uint32_t a;
    asm("{ .reg .u64 t; cvta.to.shared.u64 t, %1; cvt.u32.u64 %0, t; }" : "=r"(a) : "l"(p));
    return a;
}
__device__ __forceinline__ uint32_t mapa_u32(uint32_t laddr, uint32_t rank) {
    uint32_t r;
    asm("mapa.shared::cluster.u32 %0, %1, %2;" : "=r"(r) : "r"(laddr), "r"(rank));
    return r;
}
__device__ __forceinline__ void mbar_init(uint32_t mbar, uint32_t cnt) {
    asm volatile("mbarrier.init.shared.b64 [%0], %1;" :: "r"(mbar), "r"(cnt) : "memory");
}
__device__ __forceinline__ void mbar_expect_tx(uint32_t mbar, uint32_t bytes) {
    asm volatile("mbarrier.arrive.expect_tx.shared.b64 _, [%0], %1;"
                 :: "r"(mbar), "r"(bytes) : "memory");
}
__device__ __forceinline__ void st_async_cluster_u64(uint32_t raddr, unsigned long long v,
                                                     uint32_t rmbar) {
    asm volatile("st.async.shared::cluster.mbarrier::complete_tx::bytes.b64 [%0], %1, [%2];"
                 :: "r"(raddr), "l"(v), "r"(rmbar) : "memory");
}
__device__ __forceinline__ void mbar_wait_parity(uint32_t mbar, uint32_t parity) {
    uint32_t done;
    asm volatile(
        "{\n\t.reg .pred p;\n\t"
        "mbarrier.try_wait.parity.acquire.cta.shared::cta.b64 p, [%1], %2;\n\t"
        "selp.b32 %0, 1, 0, p;\n\t}"
        : "=r"(done) : "r"(mbar), "r"(parity) : "memory");
    if (!done) {
        asm volatile(
            "{\n\t.reg .pred P1;\n\t"
            "WL_%=:\n\t"
            "mbarrier.try_wait.parity.acquire.cta.shared::cta.b64 P1, [%0], %1, 0x989680;\n\t"
            "@P1 bra.uni WD_%=;\n\t"
            "bra.uni WL_%=;\n\t"
            "WD_%=:\n\t}"
            :: "r"(mbar), "r"(parity) : "memory");
    }
}

// tf32 split: x = hi + lo with both tf32-representable; dropped lo*lo <= 2^-24 rel.
__device__ __forceinline__ void split2(float x, uint32_t& hi, uint32_t& lo) {
    uint32_t h;
    asm("cvt.rna.tf32.f32 %0, %1;" : "=r"(h) : "f"(x));
    float r = x - __uint_as_float(h);
    uint32_t l;
    asm("cvt.rna.tf32.f32 %0, %1;" : "=r"(l) : "f"(r));
    hi = h; lo = l;
}
__device__ __forceinline__ void mma_tf32(float* c, const uint32_t* a, const uint32_t* b) {
    asm volatile(
        "mma.sync.aligned.m16n8k8.row.col.f32.tf32.tf32.f32 "
        "{%0,%1,%2,%3}, {%4,%5,%6,%7}, {%8,%9}, {%0,%1,%2,%3};"
        : "+f"(c[0]), "+f"(c[1]), "+f"(c[2]), "+f"(c[3])
        : "r"(a[0]), "r"(a[1]), "r"(a[2]), "r"(a[3]), "r"(b[0]), "r"(b[1]));
}

// ================= FPS (cluster-distributed, per-warp direct push) ================
extern __shared__ unsigned char fps_sm[];

__global__ void __cluster_dims__(CLS, 1, 1) __launch_bounds__(FT, 1)
fps_cluster_kernel(const float* __restrict__ xyz) {
    float2* xy = (float2*)fps_sm;
    float*  zz = (float*)(fps_sm + (size_t)NN * sizeof(float2));
    __shared__ alignas(16) unsigned long long cand[2][NKEY];
    __shared__ alignas(8)  unsigned long long mbar[2];

    cg::cluster_group cluster = cg::this_cluster();
    const unsigned rank = cluster.block_rank();
    const int b = blockIdx.x / CLS;
    const int t = threadIdx.x;
    const int lane = t & 31, wid = t >> 5;
    const int base = rank * SHARD;

    const float* xb = xyz + (size_t)b * NN * 3;
    for (int p = t; p < NN; p += FT) {
        xy[p] = make_float2(xb[p * 3 + 0], xb[p * 3 + 1]);
        zz[p] = xb[p * 3 + 2];
    }

    uint32_t mb0 = smem_u32(&mbar[0]);
    uint32_t mb1 = smem_u32(&mbar[1]);
    if (t == 0) {
        mbar_init(mb0, 1);
        mbar_init(mb1, 1);
        if (rank == 0) g_samp[b * NP + 0] = 0;
    }
    cluster.sync();

    float px[SLOTS], py[SLOTS], pz[SLOTS], mind[SLOTS];
#pragma unroll
    for (int s = 0; s < SLOTS; s++) {
        int p = base + t + s * FT;
        float2 a = xy[p];
        px[s] = a.x; py[s] = a.y; pz[s] = zz[p];
        mind[s] = 3.4e38f;
    }

    uint32_t rc0 = 0, rc1 = 0, rm0 = 0, rm1 = 0;
    if (lane < CLS) {
        uint32_t lc0 = smem_u32(&cand[0][rank * NW + wid]);
        uint32_t lc1 = smem_u32(&cand[1][rank * NW + wid]);
        rc0 = mapa_u32(lc0, lane);
        rc1 = mapa_u32(lc1, lane);
        rm0 = mapa_u32(mb0, lane);
        rm1 = mapa_u32(mb1, lane);
    }

    int cur = 0;
    for (int i = 1; i < NP; i++) {
        float2 cxy = xy[cur];
        float  cz  = zz[cur];
        float bestm = -1.0f; unsigned bidx = 0;
#pragma unroll
        for (int s = 0; s < SLOTS; s++) {
            float dx = px[s] - cxy.x, dy = py[s] - cxy.y, dz = pz[s] - cz;
            float d = dx * dx + dy * dy + dz * dz;     // identical expr to R11-R15
            float m = fminf(mind[s], d);
            mind[s] = m;
            if (m > bestm) { bestm = m; bidx = (unsigned)(base + t + s * FT); }
        }
        unsigned mb = __float_as_uint(bestm);
        unsigned wmax = __reduce_max_sync(0xffffffffu, mb);
        unsigned cidx = (mb == wmax) ? bidx : 0xffffffffu;
        unsigned widx = __reduce_min_sync(0xffffffffu, cidx);
        unsigned long long key =
            ((unsigned long long)wmax << 32) | (unsigned)(~widx);

        const int bi = (i - 1) & 1;
        const uint32_t ph = ((unsigned)(i - 1) >> 1) & 1u;
        if (t == 0) mbar_expect_tx(bi ? mb1 : mb0, NKEY * 8u);
        if (lane < CLS)
            st_async_cluster_u64(bi ? rc1 : rc0, key, bi ? rm1 : rm0);

        mbar_wait_parity(bi ? mb1 : mb0, ph);
        unsigned long long k0 = cand[bi][lane];
        unsigned long long k1 = cand[bi][lane + 32];
        unsigned long long k = (k1 > k0) ? k1 : k0;
        unsigned hi = (unsigned)(k >> 32), lo = (unsigned)k;
        unsigned mhi = __reduce_max_sync(0xffffffffu, hi);
        unsigned mlo = __reduce_max_sync(0xffffffffu, (hi == mhi) ? lo : 0u);
        cur = (int)(~mlo);
        if (rank == 0 && t == 0) g_samp[b * NP + i] = cur;
    }
}

// ================= gather new_xyz (also writes first section of d_out) ============
__global__ void gather_new_kernel(const float* __restrict__ xyz, float* __restrict__ out) {
    int i = blockIdx.x * blockDim.x + threadIdx.x;
    if (i >= NB * NP * 3) return;
    int bp = i / 3, k = i - bp * 3;
    int b = bp / NP;
    int idx = g_samp[bp];
    float v = xyz[((size_t)b * NN + idx) * 3 + k];
    out[i] = v;
    g_newxyz[i] = v;
}

// ================= ball query =================
__global__ void ball_query_kernel(const float* __restrict__ xyz) {
    int gw = (blockIdx.x * blockDim.x + threadIdx.x) >> 5;
    int lane = threadIdx.x & 31;
    if (gw >= NB * NP) return;
    int b = gw / NP;
    float cx = g_newxyz[gw * 3 + 0], cy = g_newxyz[gw * 3 + 1], cz = g_newxyz[gw * 3 + 2];
    const float* xb = xyz + (size_t)b * NN * 3;
    int base = gw * NS;
    int cnt = 0, first = -1;
    const float rr = 0.8f * 0.8f;
    for (int c0 = 0; c0 < NN; c0 += 32) {
        int j = c0 + lane;
        float dx = cx - xb[j * 3 + 0];
        float dy = cy - xb[j * 3 + 1];
        float dz = cz - xb[j * 3 + 2];
        float d = dx * dx + dy * dy + dz * dz;
        bool in = d < rr;
        unsigned m = __ballot_sync(0xffffffffu, in);
        if (first < 0 && m) first = c0 + (__ffs(m) - 1);
        if (in) {
            int pos = cnt + __popc(m & ((1u << lane) - 1u));
            if (pos < NS) g_nn[base + pos] = j;
        }
        cnt += __popc(m);
        if (cnt >= NS) break;
    }
    if (cnt < NS) {
        for (int k = cnt + lane; k < NS; k += 32) g_nn[base + k] = first;
    }
}

// ================= transpose features (B,C,N) -> (B,N,C) ==================
__global__ void transpose_feat_kernel(const float* __restrict__ f) {
    __shared__ float tile[32][33];
    int b = blockIdx.z;
    int n0 = blockIdx.x * 32, c0 = blockIdx.y * 32;
#pragma unroll
    for (int r = 0; r < 4; r++) {
        int c = c0 + threadIdx.y + r * 8;
        tile[threadIdx.y + r * 8][threadIdx.x] =
            f[((size_t)b * CIN + c) * NN + n0 + threadIdx.x];
    }
    __syncthreads();
#pragma unroll
    for (int r = 0; r < 4; r++) {
        int n = n0 + threadIdx.y + r * 8;
        g_featT[((size_t)b * NN + n) * CIN + c0 + threadIdx.x] =
            tile[threadIdx.x][threadIdx.y + r * 8];
    }
}

// ================= pad W1 (64x67) -> (64x80) ==================
__global__ void pad_w1_kernel(const float* __restrict__ W1) {
    int o = blockIdx.x, k = threadIdx.x;
    g_Wp1[o * KP1 + k] = (k < 67) ? W1[o * 67 + k] : 0.0f;
}

// ================= build grouped matrix G (NROWS x 80) ==================
__global__ void build_g_kernel(const float* __restrict__ xyz) {
    int row = blockIdx.x;
    int k = threadIdx.x;            // 0..79
    int b = row / (NP * NS);
    int rem = row - b * (NP * NS);
    int p = rem / NS;
    int nn = g_nn[row];
    float v = 0.0f;
    if (k < 3)       v = xyz[((size_t)b * NN + nn) * 3 + k] - g_newxyz[(b * NP + p) * 3 + k];
    else if (k < 67) v = g_featT[((size_t)b * NN + nn) * CIN + (k - 3)];
    g_G[(size_t)row * KP1 + k] = v;
}

// ================= tensor-core GEMM (tf32 split-2) + BN + ReLU =====================
// C[m,n] = relu( (sum_k A[m,k]*W[n,k]) * g[n]/sqrt(1+eps) + b[n] )
// 128x64 CTA tile, 8 warps (4m x 2n), warp tile 32x32, k-step 16.
// Smem k-major with pad (As[k][132], Bs[k][68]) -> conflict-free fragment LDS.
// LAYER 3 fuses the 32-way maxpool (row-group == warp_m) via smem atomicMax.
template<int LAYER>
__global__ void __launch_bounds__(256) mma_gemm(const float* __restrict__ W,
                                                const float* __restrict__ gs,
                                                const float* __restrict__ bt) {
    constexpr int K = (LAYER == 1) ? KP1 : ((LAYER == 2) ? 64 : 128);
    constexpr int N = (LAYER == 1) ? 64 : ((LAYER == 2) ? 128 : 256);
    const float* A = (LAYER == 1) ? (const float*)g_G
                   : (LAYER == 2) ? (const float*)g_H1 : (const float*)g_H2;
    float* C = (LAYER == 1) ? (float*)g_H1 : (float*)g_H2;   // unused for LAYER==3
    const float* Wp = (LAYER == 1) ? (const float*)g_Wp1 : W;

    __shared__ float As[16][132];
    __shared__ float Bs[16][68];
    __shared__ int red[4][64];

    int tid = threadIdx.x;
    int lane = tid & 31, wid = tid >> 5;
    int warp_m = wid & 3, warp_n = wid >> 2;
    int gid = lane >> 2, t4 = lane & 3;
    int m0 = blockIdx.x * 128, n0 = blockIdx.y * 64;

    if (LAYER == 3) red[tid >> 6][tid & 63] = 0;

    float acc[2][4][4] = {};

    for (int k0 = 0; k0 < K; k0 += 16) {
        // global loads (A: 128x16, B: 64x16)
        float4 av[2];
#pragma unroll
        for (int j = 0; j < 2; j++) {
            int idx = tid + j * 256;
            int row = idx >> 2, fc = idx & 3;
            av[j] = *(const float4*)(A + (size_t)(m0 + row) * K + k0 + fc * 4);
        }
        int bn = tid >> 2, bfc = tid & 3;
        float4 bv = *(const float4*)(Wp + (size_t)(n0 + bn) * K + k0 + bfc * 4);

        __syncthreads();   // previous k-step's fragment reads complete
#pragma unroll
        for (int j = 0; j < 2; j++) {
            int idx = tid + j * 256;
            int row = idx >> 2, fc = idx & 3;
            As[fc * 4 + 0][row] = av[j].x; As[fc * 4 + 1][row] = av[j].y;
            As[fc * 4 + 2][row] = av[j].z; As[fc * 4 + 3][row] = av[j].w;
        }
        Bs[bfc * 4 + 0][bn] = bv.x; Bs[bfc * 4 + 1][bn] = bv.y;
        Bs[bfc * 4 + 2][bn] = bv.z; Bs[bfc * 4 + 3][bn] = bv.w;
        __syncthreads();

#pragma unroll
        for (int kb = 0; kb < 16; kb += 8) {
            uint32_t bh[4][2], bl[4][2];
#pragma unroll
            for (int nt = 0; nt < 4; nt++) {
                int n = warp_n * 32 + nt * 8 + gid;
                split2(Bs[kb + t4][n],     bh[nt][0], bl[nt][0]);
                split2(Bs[kb + t4 + 4][n], bh[nt][1], bl[nt][1]);
            }
#pragma unroll
            for (int mt = 0; mt < 2; mt++) {
                int m = warp_m * 32 + mt * 16 + gid;
                uint32_t ah[4], al[4];
                split2(As[kb + t4][m],         ah[0], al[0]);
                split2(As[kb + t4][m + 8],     ah[1], al[1]);
                split2(As[kb + t4 + 4][m],     ah[2], al[2]);
                split2(As[kb + t4 + 4][m + 8], ah[3], al[3]);
#pragma unroll
                for (int nt = 0; nt < 4; nt++) {
                    mma_tf32(acc[mt][nt], ah, bh[nt]);
                    mma_tf32(acc[mt][nt], ah, bl[nt]);
                    mma_tf32(acc[mt][nt], al, bh[nt]);
                }
            }
        }
    }

    // epilogue: BN + ReLU (+ fused maxpool for LAYER 3)
    const float inv = 1.0f / sqrtf(1.0f + 1e-5f);
#pragma unroll
    for (int nt = 0; nt < 4; nt++) {
        int col = warp_n * 32 + nt * 8 + t4 * 2;      // local col (even)
        float s0 = gs[n0 + col] * inv,     b0 = bt[n0 + col];
        float s1 = gs[n0 + col + 1] * inv, b1 = bt[n0 + col + 1];
#pragma unroll
        for (int mt = 0; mt < 2; mt++) {
            int row = warp_m * 32 + mt * 16 + gid;
            float v00 = fmaxf(fmaf(acc[mt][nt][0], s0, b0), 0.0f);
            float v01 = fmaxf(fmaf(acc[mt][nt][1], s1, b1), 0.0f);
            float v10 = fmaxf(fmaf(acc[mt][nt][2], s0, b0), 0.0f);
            float v11 = fmaxf(fmaf(acc[mt][nt][3], s1, b1), 0.0f);
            if (LAYER != 3) {
                *(float2*)(C + (size_t)(m0 + row) * N + n0 + col)     = make_float2(v00, v01);
                *(float2*)(C + (size_t)(m0 + row + 8) * N + n0 + col) = make_float2(v10, v11);
            } else {
                atomicMax(&red[warp_m][col],     __float_as_int(fmaxf(v00, v10)));
                atomicMax(&red[warp_m][col + 1], __float_as_int(fmaxf(v01, v11)));
            }
        }
    }
    if (LAYER == 3) {
        __syncthreads();
        int g = tid >> 6, nn = tid & 63;
        int bp = blockIdx.x * 4 + g;                 // group row index (b*NP+p)
        g_xh[(size_t)bp * CD + n0 + nn] = __int_as_float(red[g][nn]);
    }
}

// ================= attention path (gated on alpha != 0) ==================
__global__ void squeeze_kernel(const float* __restrict__ alpha) {
    if (alpha[0] == 0.0f) return;
    int c = threadIdx.x, b = blockIdx.x;
    float m = -3.4e38f;
    for (int p = 0; p < NP; p++)
        m = fmaxf(m, g_xh[((size_t)b * NP + p) * CD + c]);
    g_s[b * CD + c] = m;
}

__global__ void excite_kernel(const float* __restrict__ We1, const float* __restrict__ We2,
                              const float* __restrict__ alpha) {
    if (alpha[0] == 0.0f) return;
    int b = blockIdx.x, t = threadIdx.x;
    __shared__ float h[32];
    if (t < 32) {
        float a = 0.0f;
        for (int i = 0; i < CD; i++) a += We1[t * CD + i] * g_s[b * CD + i];
        h[t] = fmaxf(a, 0.0f);
    }
    __syncthreads();
    float a = 0.0f;
    for (int j = 0; j < 32; j++) a += We2[t * 32 + j] * h[j];
    g_e[b * CD + t] = 1.0f / (1.0f + expf(-a));
}

__global__ void qk_kernel(const float* __restrict__ Wq, const float* __restrict__ gq,
                          const float* __restrict__ bq, const float* __restrict__ Wk,
                          const float* __restrict__ gk, const float* __restrict__ bk,
                          const float* __restrict__ alpha) {
    if (alpha[0] == 0.0f) return;
    int c = threadIdx.x, o = blockIdx.x, b = blockIdx.y, which = blockIdx.z;
    const float* W  = which ? Wk : Wq;
    const float* g  = which ? gk : gq;
    const float* bt = which ? bk : bq;
    float acc = 0.0f;
    const float* xb = g_xh + (size_t)b * NP * CD + c;
    const float* wr = W + (size_t)o * NP;
    for (int p = 0; p < NP; p++) acc += wr[p] * xb[(size_t)p * CD];
    float s = g[o] / sqrtf(1.0f + 1e-5f);
    float v = fmaxf(acc * s + bt[o], 0.0f);
    float* dst = which ? g_kt : g_qt;
    dst[((size_t)b * CD + o) * CD + c] = v;
}

__global__ void sim_softmax_kernel(const float* __restrict__ alpha) {
    if (alpha[0] == 0.0f) return;
    int c = blockIdx.x, b = blockIdx.y, d = threadIdx.x;
    __shared__ float sb[32];
    int lane = d & 31, wid = d >> 5;
    const float* kb = g_kt + (size_t)b * CD * CD;
    const float* qb = g_qt + (size_t)b * CD * CD;
    float sim = 0.0f;
    for (int q = 0; q < CD; q++) sim += kb[q * CD + c] * qb[q * CD + d];
    float mn = sim;
#pragma unroll
    for (int o = 16; o; o >>= 1) mn = fminf(mn, __shfl_xor_sync(0xffffffffu, mn, o));
    if (lane == 0) sb[wid] = mn;
    __syncthreads();
    float Mn = sb[0];
    for (int w = 1; w < 8; w++) Mn = fminf(Mn, sb[w]);
    __syncthreads();
    float num = expf(Mn - sim);
    float sm = num;
#pragma unroll
    for (int o = 16; o; o >>= 1) sm += __shfl_xor_sync(0xffffffffu, sm, o);
    if (lane == 0) sb[wid] = sm;
    __syncthreads();
    float S = 0.0f;
    for (int w = 0; w < 8; w++) S += sb[w];
    g_aff[((size_t)b * CD + c) * CD + d] = num / S;
}

// ================= final write: out[b,c,p] = alpha*(aff@v)[c,p] + x[c,p] ========
__global__ void final_write_kernel(float* __restrict__ out, const float* __restrict__ alpha) {
    int p = blockIdx.x * blockDim.x + threadIdx.x;
    int c = blockIdx.y, b = blockIdx.z;
    float a = alpha[0];
    float base = g_xh[((size_t)b * NP + p) * CD + c];
    float res = base;
    if (a != 0.0f) {
        const float* affr = g_aff + ((size_t)b * CD + c) * CD;
        const float* xhp  = g_xh + ((size_t)b * NP + p) * CD;
        const float* eb   = g_e + b * CD;
        float acc = 0.0f;
        for (int d = 0; d < CD; d++) acc += affr[d] * xhp[d] * eb[d];
        res = a * acc + base;
    }
    out[NB * NP * 3 + ((size_t)b * CD + c) * NP + p] = res;
}

// ================= host launcher ==================
extern "C" void kernel_launch(void* const* d_in, const int* in_sizes, int n_in,
                              void* d_out, int out_size) {
    const float* xyz  = (const float*)d_in[0];
    const float* feat = (const float*)d_in[1];
    const float* W1 = (const float*)d_in[2];
    const float* g1 = (const float*)d_in[3];
    const float* b1 = (const float*)d_in[4];
    const float* W2 = (const float*)d_in[5];
    const float* g2 = (const float*)d_in[6];
    const float* b2 = (const float*)d_in[7];
    const float* W3 = (const float*)d_in[8];
    const float* g3 = (const float*)d_in[9];
    const float* b3 = (const float*)d_in[10];
    const float* Wq = (const float*)d_in[11];
    const float* gq = (const float*)d_in[12];
    const float* bq = (const float*)d_in[13];
    const float* Wk = (const float*)d_in[14];
    const float* gk = (const float*)d_in[15];
    const float* bk = (const float*)d_in[16];
    const float* We1 = (const float*)d_in[17];
    const float* We2 = (const float*)d_in[18];
    const float* alpha = (const float*)d_in[19];
    float* out = (float*)d_out;

    cudaFuncSetAttribute(fps_cluster_kernel,
                         cudaFuncAttributeMaxDynamicSharedMemorySize, FPS_SMEM);

    fps_cluster_kernel<<<NB * CLS, FT, FPS_SMEM>>>(xyz);
    gather_new_kernel<<<(NB * NP * 3 + 255) / 256, 256>>>(xyz, out);
    ball_query_kernel<<<(NB * NP) / 8, 256>>>(xyz);
    transpose_feat_kernel<<<dim3(NN / 32, CIN / 32, NB), dim3(32, 8)>>>(feat);
    pad_w1_kernel<<<64, KP1>>>(W1);
    build_g_kernel<<<NROWS, KP1>>>(xyz);
    mma_gemm<1><<<dim3(NROWS / 128, 1), 256>>>(W1, g1, b1);
    mma_gemm<2><<<dim3(NROWS / 128, 2), 256>>>(W2, g2, b2);
    mma_gemm<3><<<dim3(NROWS / 128, 4), 256>>>(W3, g3, b3);   // fused maxpool -> g_xh
    // attention path (device-gated on alpha[0] != 0; alpha==0 in this dataset)
    squeeze_kernel<<<NB, CD>>>(alpha);
    excite_kernel<<<NB, CD>>>(We1, We2, alpha);
    qk_kernel<<<dim3(CD, NB, 2), CD>>>(Wq, gq, bq, Wk, gk, bk, alpha);
    sim_softmax_kernel<<<dim3(CD, NB), CD>>>(alpha);
    final_write_kernel<<<dim3(NP / 256, CD, NB), 256>>>(out, alpha);
}